// round 1
// baseline (speedup 1.0000x reference)
#include <cuda_runtime.h>

// SpikingLinearLayer fused kernel, round 0 baseline.
// out[t,b,o] = LIF scan over c[t,b,o] = sum_i x[t,b,i] * w[o,i]
// Each CTA owns a 128(batch) x 128(out) neuron tile persistently across all
// T=20 timesteps; V/I carried in registers; per-step shared-memory fp32 GEMM.

namespace {

constexpr int T_STEPS = 20;
constexpr int BATCH   = 1024;
constexpr int IN_DIM  = 2048;
constexpr int OUT_DIM = 2048;

constexpr float ALPHA_S = 0.8f;   // 1 - dt/tau_s
constexpr float ALPHA_M = 0.95f;  // 1 - dt/tau_m
constexpr float DT_TAUM = 0.05f;  // dt/tau_m
constexpr float THRESH  = 1.0f;

constexpr int BM = 128;  // batch tile
constexpr int BN = 128;  // out tile
constexpr int BK = 16;   // k tile
constexpr int TM = 8;    // per-thread rows (batch)
constexpr int TN = 8;    // per-thread cols (out)
constexpr int NTHREADS = (BM / TM) * (BN / TN);  // 256

__global__ void __launch_bounds__(NTHREADS, 1)
snn_fused_kernel(const float* __restrict__ x,
                 const float* __restrict__ w,
                 float* __restrict__ out) {
    __shared__ float As[BK][BM];  // x tile, transposed: As[k][b]
    __shared__ float Bs[BK][BN];  // w tile, transposed: Bs[k][o]

    const int tid = threadIdx.x;
    const int tx  = tid & 15;   // out-dim thread coord   (0..15)
    const int ty  = tid >> 4;   // batch-dim thread coord (0..15)
    const int b0  = blockIdx.x * BM;
    const int o0  = blockIdx.y * BN;

    // global->smem load coords: each thread loads 2 float4 per tile
    const int lrow = tid >> 2;         // 0..63
    const int lcol = (tid & 3) << 2;   // 0,4,8,12

    float V[TM][TN];
    float I[TM][TN];
#pragma unroll
    for (int i = 0; i < TM; i++)
#pragma unroll
        for (int j = 0; j < TN; j++) { V[i][j] = 0.0f; I[i][j] = 0.0f; }

    for (int t = 0; t < T_STEPS; t++) {
        float acc[TM][TN];
#pragma unroll
        for (int i = 0; i < TM; i++)
#pragma unroll
            for (int j = 0; j < TN; j++) acc[i][j] = 0.0f;

        const float* xt = x + (size_t)t * BATCH * IN_DIM;

        for (int k0 = 0; k0 < IN_DIM; k0 += BK) {
            // ---- load x tile [BM x BK] and w tile [BN x BK], transposed ----
#pragma unroll
            for (int r = 0; r < 2; r++) {
                const int row = lrow + r * 64;
                float4 xv = *reinterpret_cast<const float4*>(
                    xt + (size_t)(b0 + row) * IN_DIM + k0 + lcol);
                As[lcol + 0][row] = xv.x;
                As[lcol + 1][row] = xv.y;
                As[lcol + 2][row] = xv.z;
                As[lcol + 3][row] = xv.w;

                float4 wv = *reinterpret_cast<const float4*>(
                    w + (size_t)(o0 + row) * IN_DIM + k0 + lcol);
                Bs[lcol + 0][row] = wv.x;
                Bs[lcol + 1][row] = wv.y;
                Bs[lcol + 2][row] = wv.z;
                Bs[lcol + 3][row] = wv.w;
            }
            __syncthreads();

            // ---- 128x128x16 register-tiled FFMA ----
#pragma unroll
            for (int kk = 0; kk < BK; kk++) {
                float a[TM], bf[TN];
                float4 a0 = *reinterpret_cast<const float4*>(&As[kk][ty * TM]);
                float4 a1 = *reinterpret_cast<const float4*>(&As[kk][ty * TM + 4]);
                float4 b0v = *reinterpret_cast<const float4*>(&Bs[kk][tx * TN]);
                float4 b1v = *reinterpret_cast<const float4*>(&Bs[kk][tx * TN + 4]);
                a[0] = a0.x; a[1] = a0.y; a[2] = a0.z; a[3] = a0.w;
                a[4] = a1.x; a[5] = a1.y; a[6] = a1.z; a[7] = a1.w;
                bf[0] = b0v.x; bf[1] = b0v.y; bf[2] = b0v.z; bf[3] = b0v.w;
                bf[4] = b1v.x; bf[5] = b1v.y; bf[6] = b1v.z; bf[7] = b1v.w;
#pragma unroll
                for (int i = 0; i < TM; i++)
#pragma unroll
                    for (int j = 0; j < TN; j++)
                        acc[i][j] += a[i] * bf[j];
            }
            __syncthreads();
        }

        // ---- LIF update + spike write for this timestep ----
#pragma unroll
        for (int i = 0; i < TM; i++) {
            const int b = b0 + ty * TM + i;
            float s[TN];
#pragma unroll
            for (int j = 0; j < TN; j++) {
                I[i][j] = ALPHA_S * I[i][j] + acc[i][j];
                V[i][j] = ALPHA_M * V[i][j] + DT_TAUM * I[i][j];
                s[j] = (V[i][j] >= THRESH) ? 1.0f : 0.0f;
                V[i][j] *= (1.0f - s[j]);
            }
            float* op = out + ((size_t)t * BATCH + b) * OUT_DIM + o0 + tx * TN;
            float4 s0 = make_float4(s[0], s[1], s[2], s[3]);
            float4 s1 = make_float4(s[4], s[5], s[6], s[7]);
            *reinterpret_cast<float4*>(op)     = s0;
            *reinterpret_cast<float4*>(op + 4) = s1;
        }
    }
}

}  // namespace

extern "C" void kernel_launch(void* const* d_in, const int* in_sizes, int n_in,
                              void* d_out, int out_size) {
    const float* x = (const float*)d_in[0];   // [T, B, IN] binary fp32
    const float* w = (const float*)d_in[1];   // [OUT, IN] fp32
    float* out = (float*)d_out;               // [T, B, OUT] fp32 spikes

    dim3 grid(BATCH / BM, OUT_DIM / BN);      // 8 x 16 = 128 CTAs
    snn_fused_kernel<<<grid, NTHREADS>>>(x, w, out);
}

// round 3
// speedup vs baseline: 5.4069x; 5.4069x over previous
#include <cuda_runtime.h>
#include <cuda_bf16.h>
#include <cstdint>

// ============================================================================
// SpikingLinearLayer — mma.sync bf16 2-plane-split GEMM + LIF scan
//   (tcgen05 unavailable: harness compiles PTX for compute_103, not 103a)
//   Stage A: x fp32(binary) -> bf16                [20480 x 2048]
//   Stage B: w fp32 -> 2 bf16 planes (exact split) [2048 x 4096]
//   Stage C: C = X * Wcat^T (K=4096) -> fp32 scratch (HMMA m16n8k16)
//   Stage D: LIF scan over t, emit spikes
// ============================================================================

namespace {

constexpr int T_STEPS = 20;
constexpr int BATCH   = 1024;
constexpr int IN_DIM  = 2048;
constexpr int OUT_DIM = 2048;
constexpr int M_TOTAL = T_STEPS * BATCH;     // 20480
constexpr int K_TOTAL = 2 * IN_DIM;          // 4096 (2 bf16 planes)

constexpr float ALPHA_S = 0.8f;
constexpr float ALPHA_M = 0.95f;
constexpr float DT_TAUM = 0.05f;

// ---- scratch (device globals; no allocation) ----
__device__ __align__(1024) __nv_bfloat16 g_x_bf16[(size_t)M_TOTAL * IN_DIM];  // 84 MB
__device__ __align__(1024) __nv_bfloat16 g_w_cat[(size_t)OUT_DIM * K_TOTAL];  // 17 MB
__device__ __align__(1024) float         g_cur[(size_t)M_TOTAL * OUT_DIM];    // 168 MB

__device__ __forceinline__ uint32_t smem_u32(const void* p) {
    uint32_t a;
    asm("{ .reg .u64 t; cvta.to.shared.u64 t, %1; cvt.u32.u64 %0, t; }"
        : "=r"(a) : "l"(p));
    return a;
}

#define CP_ASYNC16(smem, gmem) \
    asm volatile("cp.async.cg.shared.global [%0], [%1], 16;" :: "r"(smem), "l"(gmem))
#define CP_COMMIT() asm volatile("cp.async.commit_group;" ::: "memory")
#define CP_WAIT(N)  asm volatile("cp.async.wait_group %0;" :: "n"(N) : "memory")

__device__ __forceinline__ void ldsm4(uint32_t& r0, uint32_t& r1, uint32_t& r2,
                                      uint32_t& r3, uint32_t addr) {
    asm volatile("ldmatrix.sync.aligned.m8n8.x4.shared.b16 {%0,%1,%2,%3}, [%4];"
                 : "=r"(r0), "=r"(r1), "=r"(r2), "=r"(r3) : "r"(addr));
}

__device__ __forceinline__ void mma16816(float* d, uint32_t a0, uint32_t a1,
                                         uint32_t a2, uint32_t a3,
                                         uint32_t b0, uint32_t b1) {
    asm volatile(
        "mma.sync.aligned.m16n8k16.row.col.f32.bf16.bf16.f32 "
        "{%0,%1,%2,%3}, {%4,%5,%6,%7}, {%8,%9}, {%0,%1,%2,%3};"
        : "+f"(d[0]), "+f"(d[1]), "+f"(d[2]), "+f"(d[3])
        : "r"(a0), "r"(a1), "r"(a2), "r"(a3), "r"(b0), "r"(b1));
}

// ============================================================================
// Stage A: x fp32 -> bf16
// ============================================================================
__global__ void convert_x_kernel(const float* __restrict__ x) {
    size_t i = ((size_t)blockIdx.x * blockDim.x + threadIdx.x) * 4;
    float4 v = *reinterpret_cast<const float4*>(x + i);
    __nv_bfloat162 lo = __floats2bfloat162_rn(v.x, v.y);
    __nv_bfloat162 hi = __floats2bfloat162_rn(v.z, v.w);
    uint2 packed = make_uint2(*reinterpret_cast<uint32_t*>(&lo),
                              *reinterpret_cast<uint32_t*>(&hi));
    *reinterpret_cast<uint2*>(g_x_bf16 + i) = packed;
}

// ============================================================================
// Stage B: w -> 2 bf16 planes (hi + exact residual), concatenated along K
// ============================================================================
__global__ void convert_w_kernel(const float* __restrict__ w) {
    size_t i = ((size_t)blockIdx.x * blockDim.x + threadIdx.x) * 4;
    int o = (int)(i / IN_DIM);
    int k = (int)(i % IN_DIM);
    float4 v = *reinterpret_cast<const float4*>(w + i);
    float vv[4] = {v.x, v.y, v.z, v.w};
    __nv_bfloat16 p0[4], p1[4];
#pragma unroll
    for (int j = 0; j < 4; j++) {
        float f = vv[j];
        __nv_bfloat16 h0 = __float2bfloat16_rn(f);
        float r1 = f - __bfloat162float(h0);
        p0[j] = h0;
        p1[j] = __float2bfloat16_rn(r1);
    }
    __nv_bfloat16* base = g_w_cat + (size_t)o * K_TOTAL + k;
    *reinterpret_cast<uint2*>(base)          = *reinterpret_cast<uint2*>(p0);
    *reinterpret_cast<uint2*>(base + IN_DIM) = *reinterpret_cast<uint2*>(p1);
}

// ============================================================================
// Stage C: GEMM  C[20480,2048] = X * Wcat^T over K=4096
//   CTA 128(M) x 256(N), BK=64, 3-stage cp.async, 8 warps @ 64x64.
// ============================================================================
constexpr int TILE_M = 128;
constexpr int TILE_N = 256;
constexpr int BK     = 64;               // 128 bytes per row
constexpr int STAGES = 3;
constexpr int NTH    = 256;
constexpr int KITERS = K_TOTAL / BK;     // 64

constexpr int A_BYTES = TILE_M * BK * 2;           // 16384
constexpr int B_BYTES = TILE_N * BK * 2;           // 32768
constexpr int STAGE_BYTES = A_BYTES + B_BYTES;     // 49152
constexpr int SMEM_BYTES = STAGES * STAGE_BYTES + 1024;  // + align slack

__device__ __forceinline__ uint32_t swz(uint32_t off) {  // SW128 within 1KB atom
    return off ^ ((off >> 3) & 0x70);
}

__global__ void __launch_bounds__(NTH, 1)
snn_gemm_kernel(float* __restrict__ cbuf) {
    extern __shared__ char smem_raw[];
    uint32_t sbase = (smem_u32(smem_raw) + 1023) & ~1023u;  // 1KB align

    const int tid  = threadIdx.x;
    const int lane = tid & 31;
    const int wid  = tid >> 5;
    const int mw   = wid & 1;        // warp m-block (0..1) -> 64 rows
    const int nw   = wid >> 1;       // warp n-block (0..3) -> 64 cols
    const int m0   = blockIdx.x * TILE_M;
    const int n0   = blockIdx.y * TILE_N;

    // ---- cp.async chunk precompute: 4 A chunks + 8 B chunks per thread ----
    const __nv_bfloat16* agp[4]; uint32_t aso[4];
#pragma unroll
    for (int j = 0; j < 4; j++) {
        int c = tid + j * 256;           // 0..1023
        int row = c >> 3, cb = c & 7;
        agp[j] = g_x_bf16 + (size_t)(m0 + row) * IN_DIM + cb * 8;
        aso[j] = swz(row * 128 + cb * 16);
    }
    const __nv_bfloat16* bgp[8]; uint32_t bso[8];
#pragma unroll
    for (int j = 0; j < 8; j++) {
        int c = tid + j * 256;           // 0..2047
        int row = c >> 3, cb = c & 7;
        bgp[j] = g_w_cat + (size_t)(n0 + row) * K_TOTAL + cb * 8;
        bso[j] = A_BYTES + swz(row * 128 + cb * 16);
    }

    auto issue_stage = [&](int s) {
        const uint32_t stg = sbase + (s % STAGES) * STAGE_BYTES;
        const int k0 = s * BK;
        const int kx = k0 & (IN_DIM - 1);   // x plane-shared K index
#pragma unroll
        for (int j = 0; j < 4; j++) CP_ASYNC16(stg + aso[j], agp[j] + kx);
#pragma unroll
        for (int j = 0; j < 8; j++) CP_ASYNC16(stg + bso[j], bgp[j] + k0);
        CP_COMMIT();
    };

    // ---- ldmatrix lane-constant offsets ----
    const int lr = lane & 15;            // row within 16-row tile
    const int halfsel = (lane >> 4) * 16;  // k-half 16B select
    uint32_t a_rowoff[4], a_xr[4];
#pragma unroll
    for (int mt = 0; mt < 4; mt++) {
        int r = mw * 64 + mt * 16 + lr;
        a_rowoff[mt] = r * 128;
        a_xr[mt] = (r & 7) * 16;
    }
    uint32_t b_rowoff[4], b_xr[4];
#pragma unroll
    for (int nt = 0; nt < 4; nt++) {
        int r = nw * 64 + nt * 16 + lr;
        b_rowoff[nt] = A_BYTES + r * 128;
        b_xr[nt] = (r & 7) * 16;
    }

    float acc[4][8][4];
#pragma unroll
    for (int i = 0; i < 4; i++)
#pragma unroll
        for (int j = 0; j < 8; j++)
#pragma unroll
            for (int q = 0; q < 4; q++) acc[i][j][q] = 0.0f;

    // ---- prologue: stages 0..STAGES-2 ----
#pragma unroll
    for (int s = 0; s < STAGES - 1; s++) issue_stage(s);

    for (int i = 0; i < KITERS; i++) {
        CP_WAIT(STAGES - 2);
        __syncthreads();
        if (i + STAGES - 1 < KITERS) issue_stage(i + STAGES - 1);

        const uint32_t stg = sbase + (i % STAGES) * STAGE_BYTES;
#pragma unroll
        for (int kk = 0; kk < 4; kk++) {
            const uint32_t kb = kk * 32 + halfsel;
            uint32_t a[4][4];
#pragma unroll
            for (int mt = 0; mt < 4; mt++)
                ldsm4(a[mt][0], a[mt][1], a[mt][2], a[mt][3],
                      stg + a_rowoff[mt] + (kb ^ a_xr[mt]));
#pragma unroll
            for (int nt = 0; nt < 4; nt++) {
                uint32_t b0, b1, b2, b3;  // b0/b2: n8-lo khalves; b1/b3: n8-hi
                ldsm4(b0, b1, b2, b3, stg + b_rowoff[nt] + (kb ^ b_xr[nt]));
#pragma unroll
                for (int mt = 0; mt < 4; mt++) {
                    mma16816(acc[mt][nt * 2 + 0], a[mt][0], a[mt][1], a[mt][2],
                             a[mt][3], b0, b2);
                    mma16816(acc[mt][nt * 2 + 1], a[mt][0], a[mt][1], a[mt][2],
                             a[mt][3], b1, b3);
                }
            }
        }
        __syncthreads();
    }

    // ---- epilogue: regs -> gmem fp32 scratch ----
    const int mrow = m0 + mw * 64 + (lane >> 2);
    const int ncol = n0 + nw * 64 + (lane & 3) * 2;
#pragma unroll
    for (int mt = 0; mt < 4; mt++) {
        float* r0 = cbuf + (size_t)(mrow + mt * 16) * OUT_DIM + ncol;
        float* r1 = r0 + 8 * OUT_DIM;
#pragma unroll
        for (int j = 0; j < 8; j++) {
            *reinterpret_cast<float2*>(r0 + j * 8) =
                make_float2(acc[mt][j][0], acc[mt][j][1]);
            *reinterpret_cast<float2*>(r1 + j * 8) =
                make_float2(acc[mt][j][2], acc[mt][j][3]);
        }
    }
}

// ============================================================================
// Stage D: LIF scan over t (memory bound)
// ============================================================================
__global__ void lif_scan_kernel(const float* __restrict__ cbuf,
                                float* __restrict__ out) {
    const size_t idx4 = ((size_t)blockIdx.x * blockDim.x + threadIdx.x) * 4;
    float4 V = make_float4(0.f, 0.f, 0.f, 0.f);
    float4 I = make_float4(0.f, 0.f, 0.f, 0.f);
#pragma unroll
    for (int t = 0; t < T_STEPS; t++) {
        const size_t off = (size_t)t * BATCH * OUT_DIM + idx4;
        float4 c = *reinterpret_cast<const float4*>(cbuf + off);
        float4 s;
        I.x = ALPHA_S * I.x + c.x;  V.x = ALPHA_M * V.x + DT_TAUM * I.x;
        s.x = (V.x >= 1.0f) ? 1.0f : 0.0f;  V.x *= (1.0f - s.x);
        I.y = ALPHA_S * I.y + c.y;  V.y = ALPHA_M * V.y + DT_TAUM * I.y;
        s.y = (V.y >= 1.0f) ? 1.0f : 0.0f;  V.y *= (1.0f - s.y);
        I.z = ALPHA_S * I.z + c.z;  V.z = ALPHA_M * V.z + DT_TAUM * I.z;
        s.z = (V.z >= 1.0f) ? 1.0f : 0.0f;  V.z *= (1.0f - s.z);
        I.w = ALPHA_S * I.w + c.w;  V.w = ALPHA_M * V.w + DT_TAUM * I.w;
        s.w = (V.w >= 1.0f) ? 1.0f : 0.0f;  V.w *= (1.0f - s.w);
        *reinterpret_cast<float4*>(out + off) = s;
    }
}

}  // namespace

extern "C" void kernel_launch(void* const* d_in, const int* in_sizes, int n_in,
                              void* d_out, int out_size) {
    const float* x = (const float*)d_in[0];   // [T, B, IN]
    const float* w = (const float*)d_in[1];   // [OUT, IN]
    float* out = (float*)d_out;               // [T, B, OUT]

    float* cbuf;
    cudaGetSymbolAddress((void**)&cbuf, g_cur);

    convert_x_kernel<<<(int)((size_t)M_TOTAL * IN_DIM / 4 / 256), 256>>>(x);
    convert_w_kernel<<<(int)((size_t)OUT_DIM * IN_DIM / 4 / 256), 256>>>(w);

    cudaFuncSetAttribute(snn_gemm_kernel,
                         cudaFuncAttributeMaxDynamicSharedMemorySize, SMEM_BYTES);
    dim3 grid(M_TOTAL / TILE_M, OUT_DIM / TILE_N);  // 160 x 8
    snn_gemm_kernel<<<grid, NTH, SMEM_BYTES>>>(cbuf);

    lif_scan_kernel<<<(int)((size_t)BATCH * OUT_DIM / 4 / 256), 256>>>(cbuf, out);
}

// round 5
// speedup vs baseline: 6.5789x; 1.2167x over previous
#include <cuda_runtime.h>
#include <cuda.h>
#include <cuda_fp16.h>
#include <cstdint>

// ============================================================================
// SpikingLinearLayer — mma.sync fp16 2-plane-split GEMM (TMA pipeline) + LIF
//   Stage A: x fp32(binary) -> fp16                 [20480 x 2048]
//   Stage B: w fp32 -> 2 fp16 planes (hi+residual)  [2048 x 4096]
//   Stage C: C = X * (W0+W1)^T -> fp32 scratch (HMMA m16n8k16.f16, TMA loads)
//   Stage D: LIF scan over t, emit spikes
// ============================================================================

namespace {

constexpr int T_STEPS = 20;
constexpr int BATCH   = 1024;
constexpr int IN_DIM  = 2048;
constexpr int OUT_DIM = 2048;
constexpr int M_TOTAL = T_STEPS * BATCH;     // 20480
constexpr int K_CAT   = 2 * IN_DIM;          // w planes concatenated: 4096

constexpr float ALPHA_S = 0.8f;
constexpr float ALPHA_M = 0.95f;
constexpr float DT_TAUM = 0.05f;

__device__ __align__(1024) __half g_x_f16[(size_t)M_TOTAL * IN_DIM];   // 84 MB
__device__ __align__(1024) __half g_w_cat[(size_t)OUT_DIM * K_CAT];    // 17 MB
__device__ __align__(1024) float  g_cur[(size_t)M_TOTAL * OUT_DIM];    // 168 MB

__device__ __forceinline__ uint32_t smem_u32(const void* p) {
    uint32_t a;
    asm("{ .reg .u64 t; cvta.to.shared.u64 t, %1; cvt.u32.u64 %0, t; }"
        : "=r"(a) : "l"(p));
    return a;
}

#define MBAR_INIT(addr, cnt) \
    asm volatile("mbarrier.init.shared.b64 [%0], %1;" :: "r"(addr), "r"(cnt) : "memory")
#define MBAR_ARRIVE(addr) \
    asm volatile("mbarrier.arrive.shared.b64 _, [%0];" :: "r"(addr) : "memory")
#define MBAR_EXPECT_TX(addr, bytes) \
    asm volatile("mbarrier.arrive.expect_tx.shared.b64 _, [%0], %1;" \
        :: "r"(addr), "r"(bytes) : "memory")
#define MBAR_WAIT(addr, ph) do {                                                   \
    uint32_t _m = (addr), _p = (ph), _d;                                           \
    asm volatile("{\n\t.reg .pred p;\n\t"                                          \
        "mbarrier.try_wait.parity.acquire.cta.shared::cta.b64 p, [%1], %2;\n\t"    \
        "selp.b32 %0, 1, 0, p;\n\t}" : "=r"(_d) : "r"(_m), "r"(_p) : "memory");    \
    if (!_d) {                                                                     \
        asm volatile("{\n\t.reg .pred P;\n\t"                                      \
        "WL_%=:\n\t"                                                               \
        "mbarrier.try_wait.parity.acquire.cta.shared::cta.b64 P, [%0], %1, 0x989680;\n\t" \
        "@P bra.uni WD_%=;\n\t"                                                    \
        "bra.uni WL_%=;\n\t"                                                       \
        "WD_%=:\n\t}" :: "r"(_m), "r"(_p) : "memory");                             \
    }                                                                              \
} while (0)

#define TMA_LOAD_2D(dst, map_addr, c0, c1, mbar) \
    asm volatile( \
        "cp.async.bulk.tensor.2d.shared::cta.global.tile.mbarrier::complete_tx::bytes " \
        "[%0], [%1, {%2, %3}], [%4];" \
        :: "r"(dst), "l"(map_addr), "r"(c0), "r"(c1), "r"(mbar) : "memory")

__device__ __forceinline__ void ldsm4(uint32_t& r0, uint32_t& r1, uint32_t& r2,
                                      uint32_t& r3, uint32_t addr) {
    asm volatile("ldmatrix.sync.aligned.m8n8.x4.shared.b16 {%0,%1,%2,%3}, [%4];"
                 : "=r"(r0), "=r"(r1), "=r"(r2), "=r"(r3) : "r"(addr));
}

__device__ __forceinline__ void mma16816(float* d, uint32_t a0, uint32_t a1,
                                         uint32_t a2, uint32_t a3,
                                         uint32_t b0, uint32_t b1) {
    asm volatile(
        "mma.sync.aligned.m16n8k16.row.col.f32.f16.f16.f32 "
        "{%0,%1,%2,%3}, {%4,%5,%6,%7}, {%8,%9}, {%0,%1,%2,%3};"
        : "+f"(d[0]), "+f"(d[1]), "+f"(d[2]), "+f"(d[3])
        : "r"(a0), "r"(a1), "r"(a2), "r"(a3), "r"(b0), "r"(b1));
}

// ============================================================================
// Stage A: x fp32 -> fp16  (binary values: exact)
// ============================================================================
__global__ void convert_x_kernel(const float* __restrict__ x) {
    size_t i = ((size_t)blockIdx.x * blockDim.x + threadIdx.x) * 4;
    float4 v = *reinterpret_cast<const float4*>(x + i);
    __half2 lo = __floats2half2_rn(v.x, v.y);
    __half2 hi = __floats2half2_rn(v.z, v.w);
    uint2 packed = make_uint2(*reinterpret_cast<uint32_t*>(&lo),
                              *reinterpret_cast<uint32_t*>(&hi));
    *reinterpret_cast<uint2*>(g_x_f16 + i) = packed;
}

// ============================================================================
// Stage B: w -> 2 fp16 planes (hi + exact residual), concatenated along K
// ============================================================================
__global__ void convert_w_kernel(const float* __restrict__ w) {
    size_t i = ((size_t)blockIdx.x * blockDim.x + threadIdx.x) * 4;
    int o = (int)(i / IN_DIM);
    int k = (int)(i % IN_DIM);
    float4 v = *reinterpret_cast<const float4*>(w + i);
    float vv[4] = {v.x, v.y, v.z, v.w};
    __half p0[4], p1[4];
#pragma unroll
    for (int j = 0; j < 4; j++) {
        float f = vv[j];
        __half h0 = __float2half_rn(f);
        float r1 = f - __half2float(h0);
        p0[j] = h0;
        p1[j] = __float2half_rn(r1);
    }
    __half* base = g_w_cat + (size_t)o * K_CAT + k;
    *reinterpret_cast<uint2*>(base)          = *reinterpret_cast<uint2*>(p0);
    *reinterpret_cast<uint2*>(base + IN_DIM) = *reinterpret_cast<uint2*>(p1);
}

// ============================================================================
// Stage C: GEMM  C[20480,2048] = X * (W0 + W1)^T
//   CTA 128(M) x 256(N); k-loop over IN_DIM in BK=64 chunks; each stage holds
//   A(16KB) + B-plane0(32KB) + B-plane1(32KB); A fragments reused for both
//   planes into the same accumulators. TMA loads, 2-stage mbarrier pipeline.
// ============================================================================
constexpr int TILE_M = 128;
constexpr int TILE_N = 256;
constexpr int BK     = 64;
constexpr int NTH    = 256;
constexpr int KITERS = IN_DIM / BK;        // 32

constexpr int A_BYTES  = TILE_M * BK * 2;  // 16384
constexpr int B_BYTES  = TILE_N * BK * 2;  // 32768 per plane
constexpr int STAGE_BYTES = A_BYTES + 2 * B_BYTES;  // 81920
constexpr int SMEM_BYTES  = 2048 + 2 * STAGE_BYTES; // align slack + ctrl

__global__ void __launch_bounds__(NTH, 1)
snn_gemm_kernel(const __grid_constant__ CUtensorMap tma_a,
                const __grid_constant__ CUtensorMap tma_b,
                float* __restrict__ cbuf) {
    extern __shared__ char smem_raw[];
    const uint32_t sbase = (smem_u32(smem_raw) + 1023) & ~1023u;
    // barriers: full[s]=sbase+s*8, empty[s]=sbase+16+s*8 ; stages at sbase+1024
    const uint32_t stg_base = sbase + 1024;

    const int tid  = threadIdx.x;
    const int lane = tid & 31;
    const int wid  = tid >> 5;
    const int mw   = wid & 1;
    const int nw   = wid >> 1;
    const int bid  = blockIdx.x;
    const int m0   = (bid >> 3) * TILE_M;   // 160 m-blocks
    const int n0   = (bid & 7) * TILE_N;    // 8 n-blocks (wave shares B in L2)

    if (tid == 0) {
#pragma unroll
        for (int s = 0; s < 2; s++) {
            MBAR_INIT(sbase + s * 8, 1);         // full: tx-based
            MBAR_INIT(sbase + 16 + s * 8, NTH);  // empty: all threads arrive
        }
    }
    __syncthreads();

    const uint64_t map_a = (uint64_t)&tma_a;
    const uint64_t map_b = (uint64_t)&tma_b;

    auto load_stage = [&](int kc) {
        const int s = kc & 1;
        const uint32_t stg = stg_base + s * STAGE_BYTES;
        const uint32_t mb = sbase + s * 8;
        MBAR_EXPECT_TX(mb, STAGE_BYTES);
        TMA_LOAD_2D(stg,                     map_a, kc * BK,           m0, mb);
        TMA_LOAD_2D(stg + A_BYTES,           map_b, kc * BK,           n0, mb);
        TMA_LOAD_2D(stg + A_BYTES + B_BYTES, map_b, IN_DIM + kc * BK,  n0, mb);
    };

    if (tid == 0) { load_stage(0); load_stage(1); }

    // ---- ldmatrix lane-constant offsets ----
    const int lr = lane & 15;
    const int halfsel = (lane >> 4) * 16;
    uint32_t a_rowoff[4], a_xr[4];
#pragma unroll
    for (int mt = 0; mt < 4; mt++) {
        int r = mw * 64 + mt * 16 + lr;
        a_rowoff[mt] = r * 128;
        a_xr[mt] = (r & 7) * 16;
    }
    uint32_t b_rowoff[4], b_xr[4];
#pragma unroll
    for (int nt = 0; nt < 4; nt++) {
        int r = nw * 64 + nt * 16 + lr;
        b_rowoff[nt] = r * 128;
        b_xr[nt] = (r & 7) * 16;
    }

    float acc[4][8][4];
#pragma unroll
    for (int i = 0; i < 4; i++)
#pragma unroll
        for (int j = 0; j < 8; j++)
#pragma unroll
            for (int q = 0; q < 4; q++) acc[i][j][q] = 0.0f;

    int pf[2] = {0, 0}, pe[2] = {0, 0};

    for (int kc = 0; kc < KITERS; kc++) {
        const int s = kc & 1;
        const uint32_t stg = stg_base + s * STAGE_BYTES;
        MBAR_WAIT(sbase + s * 8, pf[s]);
        pf[s] ^= 1;

#pragma unroll
        for (int kk = 0; kk < 4; kk++) {
            const uint32_t kb = kk * 32 + halfsel;
            uint32_t a[4][4];
#pragma unroll
            for (int mt = 0; mt < 4; mt++)
                ldsm4(a[mt][0], a[mt][1], a[mt][2], a[mt][3],
                      stg + a_rowoff[mt] + (kb ^ a_xr[mt]));
#pragma unroll
            for (int pl = 0; pl < 2; pl++) {
                const uint32_t bb = stg + A_BYTES + pl * B_BYTES;
#pragma unroll
                for (int nt = 0; nt < 4; nt++) {
                    uint32_t b0, b1, b2, b3;
                    ldsm4(b0, b1, b2, b3, bb + b_rowoff[nt] + (kb ^ b_xr[nt]));
#pragma unroll
                    for (int mt = 0; mt < 4; mt++) {
                        mma16816(acc[mt][nt * 2 + 0], a[mt][0], a[mt][1],
                                 a[mt][2], a[mt][3], b0, b2);
                        mma16816(acc[mt][nt * 2 + 1], a[mt][0], a[mt][1],
                                 a[mt][2], a[mt][3], b1, b3);
                    }
                }
            }
        }

        MBAR_ARRIVE(sbase + 16 + s * 8);
        if (tid == 0 && kc + 2 < KITERS) {
            MBAR_WAIT(sbase + 16 + s * 8, pe[s]);
            pe[s] ^= 1;
            load_stage(kc + 2);
        }
    }

    // ---- epilogue: regs -> gmem fp32 scratch ----
    const int mrow = m0 + mw * 64 + (lane >> 2);
    const int ncol = n0 + nw * 64 + (lane & 3) * 2;
#pragma unroll
    for (int mt = 0; mt < 4; mt++) {
        float* r0 = cbuf + (size_t)(mrow + mt * 16) * OUT_DIM + ncol;
        float* r1 = r0 + 8 * OUT_DIM;
#pragma unroll
        for (int j = 0; j < 8; j++) {
            *reinterpret_cast<float2*>(r0 + j * 8) =
                make_float2(acc[mt][j][0], acc[mt][j][1]);
            *reinterpret_cast<float2*>(r1 + j * 8) =
                make_float2(acc[mt][j][2], acc[mt][j][3]);
        }
    }
}

// ============================================================================
// Stage D: LIF scan over t (memory bound)
// ============================================================================
__global__ void lif_scan_kernel(const float* __restrict__ cbuf,
                                float* __restrict__ out) {
    const size_t idx4 = ((size_t)blockIdx.x * blockDim.x + threadIdx.x) * 4;
    float4 V = make_float4(0.f, 0.f, 0.f, 0.f);
    float4 I = make_float4(0.f, 0.f, 0.f, 0.f);
#pragma unroll
    for (int t = 0; t < T_STEPS; t++) {
        const size_t off = (size_t)t * BATCH * OUT_DIM + idx4;
        float4 c = *reinterpret_cast<const float4*>(cbuf + off);
        float4 s;
        I.x = ALPHA_S * I.x + c.x;  V.x = ALPHA_M * V.x + DT_TAUM * I.x;
        s.x = (V.x >= 1.0f) ? 1.0f : 0.0f;  V.x *= (1.0f - s.x);
        I.y = ALPHA_S * I.y + c.y;  V.y = ALPHA_M * V.y + DT_TAUM * I.y;
        s.y = (V.y >= 1.0f) ? 1.0f : 0.0f;  V.y *= (1.0f - s.y);
        I.z = ALPHA_S * I.z + c.z;  V.z = ALPHA_M * V.z + DT_TAUM * I.z;
        s.z = (V.z >= 1.0f) ? 1.0f : 0.0f;  V.z *= (1.0f - s.z);
        I.w = ALPHA_S * I.w + c.w;  V.w = ALPHA_M * V.w + DT_TAUM * I.w;
        s.w = (V.w >= 1.0f) ? 1.0f : 0.0f;  V.w *= (1.0f - s.w);
        *reinterpret_cast<float4*>(out + off) = s;
    }
}

}  // namespace

// ---- host-side tensormap setup (driver entry point; no -lcuda needed) ----
// Rebuilt on every kernel_launch call: deterministic, no static once-guards.
// These runtime API calls enqueue no stream work, so they are capture-safe.
typedef CUresult (*PFN_cuTensorMapEncodeTiled)(
    CUtensorMap*, CUtensorMapDataType, cuuint32_t, void*,
    const cuuint64_t*, const cuuint64_t*, const cuuint32_t*, const cuuint32_t*,
    CUtensorMapInterleave, CUtensorMapSwizzle, CUtensorMapL2promotion,
    CUtensorMapFloatOOBfill);

static CUtensorMap s_tma_a, s_tma_b;

static void build_tensormaps() {
    PFN_cuTensorMapEncodeTiled encode = nullptr;
    cudaDriverEntryPointQueryResult qres;
    cudaGetDriverEntryPoint("cuTensorMapEncodeTiled", (void**)&encode,
                            cudaEnableDefault, &qres);
    if (!encode) return;
    void* xa; cudaGetSymbolAddress(&xa, g_x_f16);
    void* wa; cudaGetSymbolAddress(&wa, g_w_cat);

    {   // A: [2048 x 20480] fp16, box [64 x 128]
        cuuint64_t dims[2]    = {(cuuint64_t)IN_DIM, (cuuint64_t)M_TOTAL};
        cuuint64_t strides[1] = {(cuuint64_t)IN_DIM * 2};
        cuuint32_t box[2]     = {BK, TILE_M};
        cuuint32_t es[2]      = {1, 1};
        encode(&s_tma_a, CU_TENSOR_MAP_DATA_TYPE_FLOAT16, 2, xa,
               dims, strides, box, es,
               CU_TENSOR_MAP_INTERLEAVE_NONE, CU_TENSOR_MAP_SWIZZLE_128B,
               CU_TENSOR_MAP_L2_PROMOTION_L2_128B,
               CU_TENSOR_MAP_FLOAT_OOB_FILL_NONE);
    }
    {   // B: [4096 x 2048] fp16, box [64 x 256]
        cuuint64_t dims[2]    = {(cuuint64_t)K_CAT, (cuuint64_t)OUT_DIM};
        cuuint64_t strides[1] = {(cuuint64_t)K_CAT * 2};
        cuuint32_t box[2]     = {BK, TILE_N};
        cuuint32_t es[2]      = {1, 1};
        encode(&s_tma_b, CU_TENSOR_MAP_DATA_TYPE_FLOAT16, 2, wa,
               dims, strides, box, es,
               CU_TENSOR_MAP_INTERLEAVE_NONE, CU_TENSOR_MAP_SWIZZLE_128B,
               CU_TENSOR_MAP_L2_PROMOTION_L2_128B,
               CU_TENSOR_MAP_FLOAT_OOB_FILL_NONE);
    }
}

extern "C" void kernel_launch(void* const* d_in, const int* in_sizes, int n_in,
                              void* d_out, int out_size) {
    const float* x = (const float*)d_in[0];   // [T, B, IN]
    const float* w = (const float*)d_in[1];   // [OUT, IN]
    float* out = (float*)d_out;               // [T, B, OUT]

    build_tensormaps();
    float* cbuf;
    cudaGetSymbolAddress((void**)&cbuf, g_cur);

    convert_x_kernel<<<(int)((size_t)M_TOTAL * IN_DIM / 4 / 256), 256>>>(x);
    convert_w_kernel<<<(int)((size_t)OUT_DIM * IN_DIM / 4 / 256), 256>>>(w);

    cudaFuncSetAttribute(snn_gemm_kernel,
                         cudaFuncAttributeMaxDynamicSharedMemorySize, SMEM_BYTES);
    snn_gemm_kernel<<<(M_TOTAL / TILE_M) * (OUT_DIM / TILE_N), NTH, SMEM_BYTES>>>(
        s_tma_a, s_tma_b, cbuf);

    lif_scan_kernel<<<(int)((size_t)BATCH * OUT_DIM / 4 / 256), 256>>>(cbuf, out);
}

// round 6
// speedup vs baseline: 6.8290x; 1.0380x over previous
#include <cuda_runtime.h>
#include <cuda.h>
#include <cuda_fp16.h>
#include <cstdint>

// ============================================================================
// SpikingLinearLayer — mma.sync fp16 2-plane-split GEMM (TMA pipeline) + LIF
//   Plane 0 (hi):       f32-accumulate HMMA
//   Plane 1 (residual): scaled by 2^10, f16-accumulate HMMA (2x rate), folded
//                       back as c = acc0 + acc1 * 2^-10 in the epilogue.
// ============================================================================

namespace {

constexpr int T_STEPS = 20;
constexpr int BATCH   = 1024;
constexpr int IN_DIM  = 2048;
constexpr int OUT_DIM = 2048;
constexpr int M_TOTAL = T_STEPS * BATCH;     // 20480
constexpr int K_CAT   = 2 * IN_DIM;          // w planes concatenated: 4096

constexpr float ALPHA_S = 0.8f;
constexpr float ALPHA_M = 0.95f;
constexpr float DT_TAUM = 0.05f;
constexpr float P1_SCALE   = 1024.0f;
constexpr float P1_INVSCALE = 0.0009765625f;   // 2^-10

__device__ __align__(1024) __half g_x_f16[(size_t)M_TOTAL * IN_DIM];   // 84 MB
__device__ __align__(1024) __half g_w_cat[(size_t)OUT_DIM * K_CAT];    // 17 MB
__device__ __align__(1024) float  g_cur[(size_t)M_TOTAL * OUT_DIM];    // 168 MB

__device__ __forceinline__ uint32_t smem_u32(const void* p) {
    uint32_t a;
    asm("{ .reg .u64 t; cvta.to.shared.u64 t, %1; cvt.u32.u64 %0, t; }"
        : "=r"(a) : "l"(p));
    return a;
}

#define MBAR_INIT(addr, cnt) \
    asm volatile("mbarrier.init.shared.b64 [%0], %1;" :: "r"(addr), "r"(cnt) : "memory")
#define MBAR_ARRIVE(addr) \
    asm volatile("mbarrier.arrive.shared.b64 _, [%0];" :: "r"(addr) : "memory")
#define MBAR_EXPECT_TX(addr, bytes) \
    asm volatile("mbarrier.arrive.expect_tx.shared.b64 _, [%0], %1;" \
        :: "r"(addr), "r"(bytes) : "memory")
#define MBAR_WAIT(addr, ph) do {                                                   \
    uint32_t _m = (addr), _p = (ph), _d;                                           \
    asm volatile("{\n\t.reg .pred p;\n\t"                                          \
        "mbarrier.try_wait.parity.acquire.cta.shared::cta.b64 p, [%1], %2;\n\t"    \
        "selp.b32 %0, 1, 0, p;\n\t}" : "=r"(_d) : "r"(_m), "r"(_p) : "memory");    \
    if (!_d) {                                                                     \
        asm volatile("{\n\t.reg .pred P;\n\t"                                      \
        "WL_%=:\n\t"                                                               \
        "mbarrier.try_wait.parity.acquire.cta.shared::cta.b64 P, [%0], %1, 0x989680;\n\t" \
        "@P bra.uni WD_%=;\n\t"                                                    \
        "bra.uni WL_%=;\n\t"                                                       \
        "WD_%=:\n\t}" :: "r"(_m), "r"(_p) : "memory");                             \
    }                                                                              \
} while (0)

#define TMA_LOAD_2D(dst, map_addr, c0, c1, mbar) \
    asm volatile( \
        "cp.async.bulk.tensor.2d.shared::cta.global.tile.mbarrier::complete_tx::bytes " \
        "[%0], [%1, {%2, %3}], [%4];" \
        :: "r"(dst), "l"(map_addr), "r"(c0), "r"(c1), "r"(mbar) : "memory")

__device__ __forceinline__ void ldsm4(uint32_t& r0, uint32_t& r1, uint32_t& r2,
                                      uint32_t& r3, uint32_t addr) {
    asm volatile("ldmatrix.sync.aligned.m8n8.x4.shared.b16 {%0,%1,%2,%3}, [%4];"
                 : "=r"(r0), "=r"(r1), "=r"(r2), "=r"(r3) : "r"(addr));
}

__device__ __forceinline__ void mma16816(float* d, uint32_t a0, uint32_t a1,
                                         uint32_t a2, uint32_t a3,
                                         uint32_t b0, uint32_t b1) {
    asm volatile(
        "mma.sync.aligned.m16n8k16.row.col.f32.f16.f16.f32 "
        "{%0,%1,%2,%3}, {%4,%5,%6,%7}, {%8,%9}, {%0,%1,%2,%3};"
        : "+f"(d[0]), "+f"(d[1]), "+f"(d[2]), "+f"(d[3])
        : "r"(a0), "r"(a1), "r"(a2), "r"(a3), "r"(b0), "r"(b1));
}

// fp16-accumulate variant (residual plane): D/C are 2 x b32 (4 x f16)
__device__ __forceinline__ void mma16816_h(uint32_t* d, uint32_t a0, uint32_t a1,
                                           uint32_t a2, uint32_t a3,
                                           uint32_t b0, uint32_t b1) {
    asm volatile(
        "mma.sync.aligned.m16n8k16.row.col.f16.f16.f16.f16 "
        "{%0,%1}, {%2,%3,%4,%5}, {%6,%7}, {%0,%1};"
        : "+r"(d[0]), "+r"(d[1])
        : "r"(a0), "r"(a1), "r"(a2), "r"(a3), "r"(b0), "r"(b1));
}

// ============================================================================
// Stage A: x fp32 -> fp16  (binary values: exact)
// ============================================================================
__global__ void convert_x_kernel(const float* __restrict__ x) {
    size_t i = ((size_t)blockIdx.x * blockDim.x + threadIdx.x) * 4;
    float4 v = *reinterpret_cast<const float4*>(x + i);
    __half2 lo = __floats2half2_rn(v.x, v.y);
    __half2 hi = __floats2half2_rn(v.z, v.w);
    uint2 packed = make_uint2(*reinterpret_cast<uint32_t*>(&lo),
                              *reinterpret_cast<uint32_t*>(&hi));
    *reinterpret_cast<uint2*>(g_x_f16 + i) = packed;
}

// ============================================================================
// Stage B: w -> plane0 fp16(w), plane1 fp16(1024*(w - plane0)); concat on K
// ============================================================================
__global__ void convert_w_kernel(const float* __restrict__ w) {
    size_t i = ((size_t)blockIdx.x * blockDim.x + threadIdx.x) * 4;
    int o = (int)(i / IN_DIM);
    int k = (int)(i % IN_DIM);
    float4 v = *reinterpret_cast<const float4*>(w + i);
    float vv[4] = {v.x, v.y, v.z, v.w};
    __half p0[4], p1[4];
#pragma unroll
    for (int j = 0; j < 4; j++) {
        float f = vv[j];
        __half h0 = __float2half_rn(f);
        float r1 = f - __half2float(h0);
        p0[j] = h0;
        p1[j] = __float2half_rn(r1 * P1_SCALE);  // scale is exact (power of 2)
    }
    __half* base = g_w_cat + (size_t)o * K_CAT + k;
    *reinterpret_cast<uint2*>(base)          = *reinterpret_cast<uint2*>(p0);
    *reinterpret_cast<uint2*>(base + IN_DIM) = *reinterpret_cast<uint2*>(p1);
}

// ============================================================================
// Stage C: GEMM  C[20480,2048] = X*W0^T + 2^-10 * (X*W1'^T)
// ============================================================================
constexpr int TILE_M = 128;
constexpr int TILE_N = 256;
constexpr int BK     = 64;
constexpr int NTH    = 256;
constexpr int KITERS = IN_DIM / BK;        // 32

constexpr int A_BYTES  = TILE_M * BK * 2;  // 16384
constexpr int B_BYTES  = TILE_N * BK * 2;  // 32768 per plane
constexpr int STAGE_BYTES = A_BYTES + 2 * B_BYTES;  // 81920
constexpr int SMEM_BYTES  = 2048 + 2 * STAGE_BYTES;

__global__ void __launch_bounds__(NTH, 1)
snn_gemm_kernel(const __grid_constant__ CUtensorMap tma_a,
                const __grid_constant__ CUtensorMap tma_b,
                float* __restrict__ cbuf) {
    extern __shared__ char smem_raw[];
    const uint32_t sbase = (smem_u32(smem_raw) + 1023) & ~1023u;
    const uint32_t stg_base = sbase + 1024;

    const int tid  = threadIdx.x;
    const int lane = tid & 31;
    const int wid  = tid >> 5;
    const int mw   = wid & 1;
    const int nw   = wid >> 1;
    const int bid  = blockIdx.x;
    const int m0   = (bid >> 3) * TILE_M;
    const int n0   = (bid & 7) * TILE_N;

    if (tid == 0) {
#pragma unroll
        for (int s = 0; s < 2; s++) {
            MBAR_INIT(sbase + s * 8, 1);         // full: tx-based
            MBAR_INIT(sbase + 16 + s * 8, NTH);  // empty: all threads arrive
        }
    }
    __syncthreads();

    const uint64_t map_a = (uint64_t)&tma_a;
    const uint64_t map_b = (uint64_t)&tma_b;

    auto load_stage = [&](int kc) {
        const int s = kc & 1;
        const uint32_t stg = stg_base + s * STAGE_BYTES;
        const uint32_t mb = sbase + s * 8;
        MBAR_EXPECT_TX(mb, STAGE_BYTES);
        TMA_LOAD_2D(stg,                     map_a, kc * BK,           m0, mb);
        TMA_LOAD_2D(stg + A_BYTES,           map_b, kc * BK,           n0, mb);
        TMA_LOAD_2D(stg + A_BYTES + B_BYTES, map_b, IN_DIM + kc * BK,  n0, mb);
    };

    if (tid == 0) { load_stage(0); load_stage(1); }

    const int lr = lane & 15;
    const int halfsel = (lane >> 4) * 16;
    uint32_t a_rowoff[4], a_xr[4];
#pragma unroll
    for (int mt = 0; mt < 4; mt++) {
        int r = mw * 64 + mt * 16 + lr;
        a_rowoff[mt] = r * 128;
        a_xr[mt] = (r & 7) * 16;
    }
    uint32_t b_rowoff[4], b_xr[4];
#pragma unroll
    for (int nt = 0; nt < 4; nt++) {
        int r = nw * 64 + nt * 16 + lr;
        b_rowoff[nt] = r * 128;
        b_xr[nt] = (r & 7) * 16;
    }

    float acc0[4][8][4];          // plane0, fp32 acc
    uint32_t acc1[4][8][2];       // plane1, fp16x2 acc
#pragma unroll
    for (int i = 0; i < 4; i++)
#pragma unroll
        for (int j = 0; j < 8; j++) {
#pragma unroll
            for (int q = 0; q < 4; q++) acc0[i][j][q] = 0.0f;
            acc1[i][j][0] = 0u; acc1[i][j][1] = 0u;
        }

    int pf[2] = {0, 0}, pe[2] = {0, 0};

    for (int kc = 0; kc < KITERS; kc++) {
        const int s = kc & 1;
        const uint32_t stg = stg_base + s * STAGE_BYTES;
        MBAR_WAIT(sbase + s * 8, pf[s]);
        pf[s] ^= 1;

#pragma unroll
        for (int kk = 0; kk < 4; kk++) {
            const uint32_t kb = kk * 32 + halfsel;
            uint32_t a[4][4];
#pragma unroll
            for (int mt = 0; mt < 4; mt++)
                ldsm4(a[mt][0], a[mt][1], a[mt][2], a[mt][3],
                      stg + a_rowoff[mt] + (kb ^ a_xr[mt]));

            // ---- plane 0: fp32 accumulate ----
            {
                const uint32_t bb = stg + A_BYTES;
#pragma unroll
                for (int nt = 0; nt < 4; nt++) {
                    uint32_t b0, b1, b2, b3;
                    ldsm4(b0, b1, b2, b3, bb + b_rowoff[nt] + (kb ^ b_xr[nt]));
#pragma unroll
                    for (int mt = 0; mt < 4; mt++) {
                        mma16816(acc0[mt][nt * 2 + 0], a[mt][0], a[mt][1],
                                 a[mt][2], a[mt][3], b0, b2);
                        mma16816(acc0[mt][nt * 2 + 1], a[mt][0], a[mt][1],
                                 a[mt][2], a[mt][3], b1, b3);
                    }
                }
            }
            // ---- plane 1 (scaled residual): fp16 accumulate ----
            {
                const uint32_t bb = stg + A_BYTES + B_BYTES;
#pragma unroll
                for (int nt = 0; nt < 4; nt++) {
                    uint32_t b0, b1, b2, b3;
                    ldsm4(b0, b1, b2, b3, bb + b_rowoff[nt] + (kb ^ b_xr[nt]));
#pragma unroll
                    for (int mt = 0; mt < 4; mt++) {
                        mma16816_h(acc1[mt][nt * 2 + 0], a[mt][0], a[mt][1],
                                   a[mt][2], a[mt][3], b0, b2);
                        mma16816_h(acc1[mt][nt * 2 + 1], a[mt][0], a[mt][1],
                                   a[mt][2], a[mt][3], b1, b3);
                    }
                }
            }
        }

        MBAR_ARRIVE(sbase + 16 + s * 8);
        if (tid == 0 && kc + 2 < KITERS) {
            MBAR_WAIT(sbase + 16 + s * 8, pe[s]);
            pe[s] ^= 1;
            load_stage(kc + 2);
        }
    }

    // ---- epilogue: c = acc0 + acc1 * 2^-10 ----
    const int mrow = m0 + mw * 64 + (lane >> 2);
    const int ncol = n0 + nw * 64 + (lane & 3) * 2;
#pragma unroll
    for (int mt = 0; mt < 4; mt++) {
        float* r0 = cbuf + (size_t)(mrow + mt * 16) * OUT_DIM + ncol;
        float* r1 = r0 + 8 * OUT_DIM;
#pragma unroll
        for (int j = 0; j < 8; j++) {
            float2 lo = __half22float2(
                *reinterpret_cast<const __half2*>(&acc1[mt][j][0]));
            float2 hi = __half22float2(
                *reinterpret_cast<const __half2*>(&acc1[mt][j][1]));
            *reinterpret_cast<float2*>(r0 + j * 8) =
                make_float2(fmaf(lo.x, P1_INVSCALE, acc0[mt][j][0]),
                            fmaf(lo.y, P1_INVSCALE, acc0[mt][j][1]));
            *reinterpret_cast<float2*>(r1 + j * 8) =
                make_float2(fmaf(hi.x, P1_INVSCALE, acc0[mt][j][2]),
                            fmaf(hi.y, P1_INVSCALE, acc0[mt][j][3]));
        }
    }
}

// ============================================================================
// Stage D: LIF scan over t (memory bound)
// ============================================================================
__global__ void lif_scan_kernel(const float* __restrict__ cbuf,
                                float* __restrict__ out) {
    const size_t idx4 = ((size_t)blockIdx.x * blockDim.x + threadIdx.x) * 4;
    float4 V = make_float4(0.f, 0.f, 0.f, 0.f);
    float4 I = make_float4(0.f, 0.f, 0.f, 0.f);
#pragma unroll
    for (int t = 0; t < T_STEPS; t++) {
        const size_t off = (size_t)t * BATCH * OUT_DIM + idx4;
        float4 c = *reinterpret_cast<const float4*>(cbuf + off);
        float4 s;
        I.x = ALPHA_S * I.x + c.x;  V.x = ALPHA_M * V.x + DT_TAUM * I.x;
        s.x = (V.x >= 1.0f) ? 1.0f : 0.0f;  V.x *= (1.0f - s.x);
        I.y = ALPHA_S * I.y + c.y;  V.y = ALPHA_M * V.y + DT_TAUM * I.y;
        s.y = (V.y >= 1.0f) ? 1.0f : 0.0f;  V.y *= (1.0f - s.y);
        I.z = ALPHA_S * I.z + c.z;  V.z = ALPHA_M * V.z + DT_TAUM * I.z;
        s.z = (V.z >= 1.0f) ? 1.0f : 0.0f;  V.z *= (1.0f - s.z);
        I.w = ALPHA_S * I.w + c.w;  V.w = ALPHA_M * V.w + DT_TAUM * I.w;
        s.w = (V.w >= 1.0f) ? 1.0f : 0.0f;  V.w *= (1.0f - s.w);
        *reinterpret_cast<float4*>(out + off) = s;
    }
}

}  // namespace

// ---- host-side tensormap setup (rebuilt every call; no static guards) ----
typedef CUresult (*PFN_cuTensorMapEncodeTiled)(
    CUtensorMap*, CUtensorMapDataType, cuuint32_t, void*,
    const cuuint64_t*, const cuuint64_t*, const cuuint32_t*, const cuuint32_t*,
    CUtensorMapInterleave, CUtensorMapSwizzle, CUtensorMapL2promotion,
    CUtensorMapFloatOOBfill);

static CUtensorMap s_tma_a, s_tma_b;

static void build_tensormaps() {
    PFN_cuTensorMapEncodeTiled encode = nullptr;
    cudaDriverEntryPointQueryResult qres;
    cudaGetDriverEntryPoint("cuTensorMapEncodeTiled", (void**)&encode,
                            cudaEnableDefault, &qres);
    if (!encode) return;
    void* xa; cudaGetSymbolAddress(&xa, g_x_f16);
    void* wa; cudaGetSymbolAddress(&wa, g_w_cat);

    {   // A: [2048 x 20480] fp16, box [64 x 128]
        cuuint64_t dims[2]    = {(cuuint64_t)IN_DIM, (cuuint64_t)M_TOTAL};
        cuuint64_t strides[1] = {(cuuint64_t)IN_DIM * 2};
        cuuint32_t box[2]     = {BK, TILE_M};
        cuuint32_t es[2]      = {1, 1};
        encode(&s_tma_a, CU_TENSOR_MAP_DATA_TYPE_FLOAT16, 2, xa,
               dims, strides, box, es,
               CU_TENSOR_MAP_INTERLEAVE_NONE, CU_TENSOR_MAP_SWIZZLE_128B,
               CU_TENSOR_MAP_L2_PROMOTION_L2_128B,
               CU_TENSOR_MAP_FLOAT_OOB_FILL_NONE);
    }
    {   // B: [4096 x 2048] fp16, box [64 x 256]
        cuuint64_t dims[2]    = {(cuuint64_t)K_CAT, (cuuint64_t)OUT_DIM};
        cuuint64_t strides[1] = {(cuuint64_t)K_CAT * 2};
        cuuint32_t box[2]     = {BK, TILE_N};
        cuuint32_t es[2]      = {1, 1};
        encode(&s_tma_b, CU_TENSOR_MAP_DATA_TYPE_FLOAT16, 2, wa,
               dims, strides, box, es,
               CU_TENSOR_MAP_INTERLEAVE_NONE, CU_TENSOR_MAP_SWIZZLE_128B,
               CU_TENSOR_MAP_L2_PROMOTION_L2_128B,
               CU_TENSOR_MAP_FLOAT_OOB_FILL_NONE);
    }
}

extern "C" void kernel_launch(void* const* d_in, const int* in_sizes, int n_in,
                              void* d_out, int out_size) {
    const float* x = (const float*)d_in[0];   // [T, B, IN]
    const float* w = (const float*)d_in[1];   // [OUT, IN]
    float* out = (float*)d_out;               // [T, B, OUT]

    build_tensormaps();
    float* cbuf;
    cudaGetSymbolAddress((void**)&cbuf, g_cur);

    convert_x_kernel<<<(int)((size_t)M_TOTAL * IN_DIM / 4 / 256), 256>>>(x);
    convert_w_kernel<<<(int)((size_t)OUT_DIM * IN_DIM / 4 / 256), 256>>>(w);

    cudaFuncSetAttribute(snn_gemm_kernel,
                         cudaFuncAttributeMaxDynamicSharedMemorySize, SMEM_BYTES);
    snn_gemm_kernel<<<(M_TOTAL / TILE_M) * (OUT_DIM / TILE_N), NTH, SMEM_BYTES>>>(
        s_tma_a, s_tma_b, cbuf);

    lif_scan_kernel<<<(int)((size_t)BATCH * OUT_DIM / 4 / 256), 256>>>(cbuf, out);
}